// round 2
// baseline (speedup 1.0000x reference)
#include <cuda_runtime.h>
#include <math.h>

#define BB 32
#define LL 512
#define NN 1023
#define HH 128
#define EE 126

// Scratch (device globals — no allocations allowed)
__device__ float g_duo[BB * NN * 256];   // [b][node][0:128 down | 128:256 up]  ~33.5MB
__device__ float g_leaf[BB * LL * 128];  // leaf input features                  ~8.4MB
__device__ float g_WcT[256 * 128];       // WcT[j][i] = Wc[i][j]
__device__ float g_WdT[256 * 256];
__device__ float g_WgT[128 * 128];

// ---------- f32x2 helpers (Blackwell packed fp32 FMA) ----------
__device__ __forceinline__ unsigned long long pk2(float lo, float hi) {
    unsigned long long r;
    asm("mov.b64 %0, {%1,%2};" : "=l"(r) : "f"(lo), "f"(hi));
    return r;
}
__device__ __forceinline__ void fma2(unsigned long long& d, unsigned long long a, unsigned long long b) {
    asm("fma.rn.f32x2 %0, %1, %2, %0;" : "+l"(d) : "l"(a), "l"(b));
}
__device__ __forceinline__ void unpk2(unsigned long long v, float& a, float& b) {
    asm("mov.b64 {%0,%1}, %2;" : "=f"(a), "=f"(b) : "l"(v));
}

// ---------- setup: weight transposes + leaf features + leaf up=0 ----------
// grid.x = 1024 blocks x 256 threads; first 256 blocks do leaf feats,
// remaining threads strided over the transposes.
__global__ __launch_bounds__(256) void ksetup(const int* __restrict__ x,
                                              const int* __restrict__ cue,
                                              const float* __restrict__ emb,
                                              const float* __restrict__ Wc,
                                              const float* __restrict__ Wd,
                                              const float* __restrict__ Wg) {
    int t = blockIdx.x * 256 + threadIdx.x;
    // leaf features: B*L*128 = 2,097,152 elements
    if (t < BB * LL * 128) {
        int i = t & 127;
        int l = (t >> 7) & (LL - 1);
        int b = t >> 16;
        int node = (LL - 1) + l;
        float v;
        if (i < EE) v = emb[(long long)x[b * NN + node] * EE + i];
        else        v = (cue[b * NN + node] == (i - EE)) ? 1.0f : 0.0f;
        g_leaf[t] = v;
        g_duo[(b * NN + node) * 256 + 128 + i] = 0.0f;   // leaves: up = 0
    }
    // transposes (strided over whole grid; cheap)
    int stride = gridDim.x * 256;
    for (int idx = t; idx < 256 * 128; idx += stride) {
        int j = idx >> 7, i = idx & 127;
        g_WcT[idx] = Wc[i * 256 + j];
    }
    for (int idx = t; idx < 256 * 256; idx += stride) {
        int j = idx >> 8, i = idx & 255;
        g_WdT[idx] = Wd[i * 256 + j];
    }
    for (int idx = t; idx < 128 * 128; idx += stride) {
        int j = idx >> 7, i = idx & 127;
        g_WgT[idx] = Wg[i * 128 + j];
    }
}

// ---------- generic level GEMM ----------
// OUT[M,128-tile] = tanh(A[M,256] @ WT + bias), M = B * 2^logR
// MODE 0: up d=8, A from g_leaf (contiguous 256)
// MODE 1: up d<8, A = concat(up[2p+1], up[2p+2]) (two 128-seg gathers)
// MODE 2: down,   A = duo row of parent p (contiguous 256); blockIdx.y picks child half
template <int BM, int TR, int MODE>
__global__ __launch_bounds__(256) void kgemm(int sel, const float* __restrict__ bias,
                                             int logR, int off, int Ntot) {
    const float* __restrict__ WT = sel ? g_WdT : g_WcT;
    __shared__ float sa[32][BM + 4];
    __shared__ float sw[32][132];
    const int tid = threadIdx.x;
    const int rt = tid >> 4;    // 0..15
    const int ct = tid & 15;    // 0..15
    const int colBase = blockIdx.y * 128;
    const int rowBase = blockIdx.x * BM;
    const int Rm1 = (1 << logR) - 1;

    // per-thread A-loader base pointer (one tile row per 8 loading threads)
    const float* abase = nullptr;
    if (tid < BM * 8) {
        int lr = tid >> 3;
        int m = rowBase + lr;
        int b = m >> logR, pi = m & Rm1;
        if (MODE == 0)      abase = g_leaf + ((b << 9) + (pi << 1)) * 128;
        else if (MODE == 1) abase = g_duo + (b * NN + 2 * (off + pi) + 1) * 256 + 128;
        else                abase = g_duo + (b * NN + (off + pi)) * 256;
    }
    const int q = tid & 7;

    unsigned long long acc[TR][4];
#pragma unroll
    for (int r = 0; r < TR; ++r)
#pragma unroll
        for (int c = 0; c < 4; ++c) acc[r][c] = 0ULL;

    for (int ch = 0; ch < 8; ++ch) {
        int k0 = ch * 32;
        if (tid < BM * 8) {
            int k = k0 + q * 4;
            const float* src = abase + k + ((MODE == 1) ? ((k >> 7) << 7) : 0);
            float4 v = *(const float4*)src;
            int lr = tid >> 3;
            sa[q * 4 + 0][lr] = v.x;
            sa[q * 4 + 1][lr] = v.y;
            sa[q * 4 + 2][lr] = v.z;
            sa[q * 4 + 3][lr] = v.w;
        }
#pragma unroll
        for (int i = 0; i < 4; ++i) {
            int f = tid + i * 256;
            int kk = f >> 5, c4 = f & 31;
            float4 v = *(const float4*)&WT[(k0 + kk) * Ntot + colBase + c4 * 4];
            *(float4*)&sw[kk][c4 * 4] = v;
        }
        __syncthreads();
#pragma unroll
        for (int kk = 0; kk < 32; ++kk) {
            ulonglong2 w0 = *(const ulonglong2*)&sw[kk][ct * 8];
            ulonglong2 w1 = *(const ulonglong2*)&sw[kk][ct * 8 + 4];
            if (TR == 2) {
                float2 av = *(const float2*)&sa[kk][rt * 2];
                unsigned long long a0 = pk2(av.x, av.x);
                unsigned long long a1 = pk2(av.y, av.y);
                fma2(acc[0][0], a0, w0.x); fma2(acc[0][1], a0, w0.y);
                fma2(acc[0][2], a0, w1.x); fma2(acc[0][3], a0, w1.y);
                fma2(acc[1][0], a1, w0.x); fma2(acc[1][1], a1, w0.y);
                fma2(acc[1][2], a1, w1.x); fma2(acc[1][3], a1, w1.y);
            } else {
                float a = sa[kk][rt];
                unsigned long long a0 = pk2(a, a);
                fma2(acc[0][0], a0, w0.x); fma2(acc[0][1], a0, w0.y);
                fma2(acc[0][2], a0, w1.x); fma2(acc[0][3], a0, w1.y);
            }
        }
        __syncthreads();
    }

#pragma unroll
    for (int r = 0; r < TR; ++r) {
        int m = rowBase + rt * TR + r;
        int b = m >> logR, pi = m & Rm1;
        float* dst;
        if (MODE == 2) dst = g_duo + (b * NN + 2 * (off + pi) + 1 + blockIdx.y) * 256;
        else           dst = g_duo + (b * NN + (off + pi)) * 256 + 128;
#pragma unroll
        for (int c = 0; c < 4; ++c) {
            float v0, v1;
            unpk2(acc[r][c], v0, v1);
            int col = ct * 8 + c * 2;
            v0 = tanhf(v0 + bias[colBase + col]);
            v1 = tanhf(v1 + bias[colBase + col + 1]);
            *(float2*)&dst[col] = make_float2(v0, v1);
        }
    }
}

// ---------- fused top of tree: up levels 3..0, root gate, down levels 0..2 ----------
__global__ __launch_bounds__(256) void kmid(const float* __restrict__ bc,
                                            const float* __restrict__ bd,
                                            const float* __restrict__ bg) {
    __shared__ float su[31 * 128];  // up values for nodes 0..30
    __shared__ float sd[15 * 128];  // down values for nodes 0..14
    int b = blockIdx.x;
    int tid = threadIdx.x;
    float* duoB = g_duo + (long long)b * NN * 256;

    for (int idx = tid; idx < 16 * 128; idx += 256) {
        int n = 15 + (idx >> 7), c = idx & 127;
        su[n * 128 + c] = duoB[n * 256 + 128 + c];
    }
    __syncthreads();

    // upward levels 3..0
    for (int k = 3; k >= 0; --k) {
        int p0 = (1 << k) - 1, P = 1 << k;
        int col = tid & 127;
        for (int pi = tid >> 7; pi < P; pi += 2) {
            int p = p0 + pi;
            const float* ctx = &su[(2 * p + 1) * 128];
            float a0 = bc[col], a1 = 0.f, a2 = 0.f, a3 = 0.f;
#pragma unroll 8
            for (int j = 0; j < 256; j += 4) {
                a0 = fmaf(ctx[j + 0], g_WcT[(j + 0) * 128 + col], a0);
                a1 = fmaf(ctx[j + 1], g_WcT[(j + 1) * 128 + col], a1);
                a2 = fmaf(ctx[j + 2], g_WcT[(j + 2) * 128 + col], a2);
                a3 = fmaf(ctx[j + 3], g_WcT[(j + 3) * 128 + col], a3);
            }
            float v = tanhf((a0 + a1) + (a2 + a3));
            su[p * 128 + col] = v;
            duoB[p * 256 + 128 + col] = v;
        }
        __syncthreads();
    }

    // root gate: down[0] = sigmoid(Wg h0 + bg)
    if (tid < 128) {
        int col = tid;
        float a0 = bg[col], a1 = 0.f, a2 = 0.f, a3 = 0.f;
#pragma unroll 8
        for (int j = 0; j < 128; j += 4) {
            a0 = fmaf(su[j + 0], g_WgT[(j + 0) * 128 + col], a0);
            a1 = fmaf(su[j + 1], g_WgT[(j + 1) * 128 + col], a1);
            a2 = fmaf(su[j + 2], g_WgT[(j + 2) * 128 + col], a2);
            a3 = fmaf(su[j + 3], g_WgT[(j + 3) * 128 + col], a3);
        }
        float v = 1.f / (1.f + expf(-((a0 + a1) + (a2 + a3))));
        sd[col] = v;
        duoB[col] = v;
    }
    __syncthreads();

    // downward levels 0..2 (writes down for nodes 1..14)
    for (int k = 0; k <= 2; ++k) {
        int p0 = (1 << k) - 1, P = 1 << k;
        int col = tid;  // 256 output cols
        for (int pi = 0; pi < P; ++pi) {
            int p = p0 + pi;
            const float* dctx = &sd[p * 128];
            const float* uctx = &su[p * 128];
            float a0 = bd[col], a1 = 0.f, a2 = 0.f, a3 = 0.f;
#pragma unroll 8
            for (int j = 0; j < 128; j += 4) {
                a0 = fmaf(dctx[j + 0], g_WdT[(j + 0) * 256 + col], a0);
                a1 = fmaf(dctx[j + 1], g_WdT[(j + 1) * 256 + col], a1);
                a2 = fmaf(dctx[j + 2], g_WdT[(j + 2) * 256 + col], a2);
                a3 = fmaf(dctx[j + 3], g_WdT[(j + 3) * 256 + col], a3);
            }
#pragma unroll 8
            for (int j = 0; j < 128; j += 4) {
                a0 = fmaf(uctx[j + 0], g_WdT[(128 + j + 0) * 256 + col], a0);
                a1 = fmaf(uctx[j + 1], g_WdT[(128 + j + 1) * 256 + col], a1);
                a2 = fmaf(uctx[j + 2], g_WdT[(128 + j + 2) * 256 + col], a2);
                a3 = fmaf(uctx[j + 3], g_WdT[(128 + j + 3) * 256 + col], a3);
            }
            float v = tanhf((a0 + a1) + (a2 + a3));
            int child = 2 * p + 1 + (col >> 7);
            int cc = col & 127;
            sd[child * 128 + cc] = v;
            duoB[child * 256 + cc] = v;
        }
        __syncthreads();
    }
}

// ---------- classifier + softmax (one warp per node) ----------
__global__ __launch_bounds__(256) void kcls(const float* __restrict__ Wcl,
                                            const float* __restrict__ bcl,
                                            float* __restrict__ out) {
    int warp = (blockIdx.x * 256 + threadIdx.x) >> 5;
    int lane = threadIdx.x & 31;
    if (warp >= BB * NN) return;
    const float* row = g_duo + (long long)warp * 256;
    float s0 = 0.f, s1 = 0.f;
#pragma unroll
    for (int h = 0; h < 2; ++h) {
        float4 v = *(const float4*)&row[lane * 8 + h * 4];
        float4 a = *(const float4*)&Wcl[lane * 8 + h * 4];
        float4 c = *(const float4*)&Wcl[256 + lane * 8 + h * 4];
        s0 += v.x * a.x + v.y * a.y + v.z * a.z + v.w * a.w;
        s1 += v.x * c.x + v.y * c.y + v.z * c.z + v.w * c.w;
    }
#pragma unroll
    for (int o = 16; o; o >>= 1) {
        s0 += __shfl_xor_sync(0xFFFFFFFFu, s0, o);
        s1 += __shfl_xor_sync(0xFFFFFFFFu, s1, o);
    }
    if (lane == 0) {
        s0 = 1.f / (1.f + expf(-(s0 + bcl[0])));
        s1 = 1.f / (1.f + expf(-(s1 + bcl[1])));
        float e0 = expf(s0), e1 = expf(s1);
        float inv = 1.f / (e0 + e1);
        out[warp * 2 + 0] = e0 * inv;
        out[warp * 2 + 1] = e1 * inv;
    }
}

extern "C" void kernel_launch(void* const* d_in, const int* in_sizes, int n_in,
                              void* d_out, int out_size) {
    const int*   x    = (const int*)d_in[0];
    // d_in[1] word_index: identity leaf map per dataset; d_in[3] adj: redundant heap encoding
    const int*   cue  = (const int*)d_in[2];
    const float* emb  = (const float*)d_in[4];
    const float* Wc   = (const float*)d_in[5];
    const float* bc   = (const float*)d_in[6];
    const float* Wd   = (const float*)d_in[7];
    const float* bd   = (const float*)d_in[8];
    const float* Wg   = (const float*)d_in[9];
    const float* bg   = (const float*)d_in[10];
    const float* Wcl  = (const float*)d_in[11];
    const float* bcl  = (const float*)d_in[12];
    float* out = (float*)d_out;

    ksetup<<<(BB * LL * 128) / 256, 256>>>(x, cue, emb, Wc, Wd, Wg);

    // upward (parents at level d compose from level d+1)
    kgemm<32, 2, 0><<<dim3(256, 1), 256>>>(0, bc, 8, 255, 128);  // M=8192
    kgemm<32, 2, 1><<<dim3(128, 1), 256>>>(0, bc, 7, 127, 128);  // M=4096
    kgemm<16, 1, 1><<<dim3(128, 1), 256>>>(0, bc, 6, 63, 128);   // M=2048
    kgemm<16, 1, 1><<<dim3(64, 1), 256>>>(0, bc, 5, 31, 128);    // M=1024
    kgemm<16, 1, 1><<<dim3(32, 1), 256>>>(0, bc, 4, 15, 128);    // M=512

    kmid<<<BB, 256>>>(bc, bd, bg);

    // downward (parents at level d produce children at level d+1)
    kgemm<16, 1, 2><<<dim3(16, 2), 256>>>(1, bd, 3, 7, 256);     // M=256
    kgemm<16, 1, 2><<<dim3(32, 2), 256>>>(1, bd, 4, 15, 256);    // M=512
    kgemm<16, 1, 2><<<dim3(64, 2), 256>>>(1, bd, 5, 31, 256);    // M=1024
    kgemm<16, 1, 2><<<dim3(128, 2), 256>>>(1, bd, 6, 63, 256);   // M=2048
    kgemm<32, 2, 2><<<dim3(128, 2), 256>>>(1, bd, 7, 127, 256);  // M=4096
    kgemm<32, 2, 2><<<dim3(256, 2), 256>>>(1, bd, 8, 255, 256);  // M=8192

    kcls<<<(BB * NN + 7) / 8, 256>>>(Wcl, bcl, out);
}

// round 4
// speedup vs baseline: 1.3041x; 1.3041x over previous
#include <cuda_runtime.h>
#include <math.h>

#define BB 32
#define LL 512
#define NN 1023
#define EE 126
#define KC 16

// Scratch (device globals — no allocations allowed)
__device__ float g_duo[BB * NN * 256];   // [b][node][0:128 down | 128:256 up]
__device__ float g_leaf[BB * LL * 128];  // leaf input features
__device__ float g_WcT[256 * 128];       // WcT[j][i] = Wc[i][j]
__device__ float g_WdT[256 * 256];
__device__ float g_WgT[128 * 128];

// ---------- f32x2 helpers ----------
__device__ __forceinline__ unsigned long long pk2(float lo, float hi) {
    unsigned long long r;
    asm("mov.b64 %0, {%1,%2};" : "=l"(r) : "f"(lo), "f"(hi));
    return r;
}
__device__ __forceinline__ void fma2(unsigned long long& d, unsigned long long a, unsigned long long b) {
    asm("fma.rn.f32x2 %0, %1, %2, %0;" : "+l"(d) : "l"(a), "l"(b));
}
__device__ __forceinline__ void unpk2(unsigned long long v, float& a, float& b) {
    asm("mov.b64 {%0,%1}, %2;" : "=f"(a), "=f"(b) : "l"(v));
}
__device__ __forceinline__ float tanh_fast(float x) {
    float e = __expf(2.0f * x);
    return 1.0f - __fdividef(2.0f, e + 1.0f);
}
__device__ __forceinline__ float sigmoid_fast(float x) {
    return __fdividef(1.0f, 1.0f + __expf(-x));
}

// ---------- setup: weight transposes + leaf features + leaf up=0 ----------
__global__ __launch_bounds__(256) void ksetup(const int* __restrict__ x,
                                              const int* __restrict__ cue,
                                              const float* __restrict__ emb,
                                              const float* __restrict__ Wc,
                                              const float* __restrict__ Wd,
                                              const float* __restrict__ Wg) {
    int t = blockIdx.x * 256 + threadIdx.x;
    if (t < BB * LL * 128) {
        int i = t & 127;
        int l = (t >> 7) & (LL - 1);
        int b = t >> 16;
        int node = (LL - 1) + l;
        float v;
        if (i < EE) v = emb[(long long)x[b * NN + node] * EE + i];
        else        v = (cue[b * NN + node] == (i - EE)) ? 1.0f : 0.0f;
        g_leaf[t] = v;
        g_duo[(b * NN + node) * 256 + 128 + i] = 0.0f;
    }
    int stride = gridDim.x * 256;
    for (int idx = t; idx < 256 * 128; idx += stride) {
        int j = idx >> 7, i = idx & 127;
        g_WcT[idx] = Wc[i * 256 + j];
    }
    for (int idx = t; idx < 256 * 256; idx += stride) {
        int j = idx >> 8, i = idx & 255;
        g_WdT[idx] = Wd[i * 256 + j];
    }
    for (int idx = t; idx < 128 * 128; idx += stride) {
        int j = idx >> 7, i = idx & 127;
        g_WgT[idx] = Wg[i * 128 + j];
    }
}

// ---------- high-ILP level GEMM ----------
// OUT[M, 128-tile] = tanh(A[M,256] @ WT[:, colBase:colBase+128] + bias)
// Block: 128 threads; tile 64 rows x 128 cols; thread: 8 rows x 8 cols (32 f32x2 acc).
// MODE 0: up d=8, A from g_leaf (contiguous 256)
// MODE 1: up d<8, A = concat(up[2p+1], up[2p+2])
// MODE 2: down,   A = duo row of parent (contiguous 256); y picks child/col-half
template <int MODE>
__global__ __launch_bounds__(128, 3) void kgemm2(int sel, const float* __restrict__ bias,
                                                 int logR, int off, int Ntot) {
    __shared__ __align__(16) float sa[2][KC][68];
    __shared__ __align__(16) float sw[2][KC][140];
    const float* __restrict__ WT = sel ? g_WdT : g_WcT;
    const int tid = threadIdx.x;
    const int cg = tid & 15;       // col group: cols cg*8 .. cg*8+7
    const int rg = tid >> 4;       // row group: rows rg*8 .. rg*8+7
    const int y = blockIdx.y;
    const int colBase = y << 7;
    const int rowBase = blockIdx.x * 64;
    const int Rm1 = (1 << logR) - 1;

    // A loader: thread handles row lr, k-halfchunk halfk
    const int lr = tid >> 1;
    const int halfk = (tid & 1) * 8;
    const float* abase;
    {
        int m = rowBase + lr;
        int b = m >> logR, pi = m & Rm1;
        if (MODE == 0)      abase = g_leaf + (((b << 9) + (pi << 1)) << 7);
        else if (MODE == 1) abase = g_duo + (b * NN + 2 * (off + pi) + 1) * 256 + 128;
        else                abase = g_duo + (b * NN + (off + pi)) * 256;
    }
    unsigned swbase = (unsigned)__cvta_generic_to_shared(&sw[0][0][0]);

    float4 areg0, areg1;

#define ISSUE_W(CH, BUF)                                                              \
    {                                                                                 \
        _Pragma("unroll")                                                             \
        for (int i = 0; i < 4; i++) {                                                 \
            int f = tid + i * 128;                                                    \
            int kk = f >> 5, c4 = f & 31;                                             \
            const float* src = WT + ((CH) * KC + kk) * Ntot + colBase + c4 * 4;       \
            unsigned dst = swbase + ((BUF) * KC * 140 + kk * 140 + (c4 + (c4 >> 3)) * 4) * 4; \
            asm volatile("cp.async.cg.shared.global [%0], [%1], 16;" ::"r"(dst), "l"(src)); \
        }                                                                             \
        asm volatile("cp.async.commit_group;");                                       \
    }

#define LDG_A(CH)                                                                     \
    {                                                                                 \
        int kg0 = (CH) * KC + halfk;                                                  \
        int extra = (MODE == 1) ? ((kg0 >> 7) << 7) : 0;                              \
        const float* p = abase + kg0 + extra;                                         \
        areg0 = *(const float4*)p;                                                    \
        areg1 = *(const float4*)(p + 4);                                              \
    }

#define STS_A(BUF)                                                                    \
    {                                                                                 \
        sa[BUF][halfk + 0][lr] = areg0.x; sa[BUF][halfk + 1][lr] = areg0.y;           \
        sa[BUF][halfk + 2][lr] = areg0.z; sa[BUF][halfk + 3][lr] = areg0.w;           \
        sa[BUF][halfk + 4][lr] = areg1.x; sa[BUF][halfk + 5][lr] = areg1.y;           \
        sa[BUF][halfk + 6][lr] = areg1.z; sa[BUF][halfk + 7][lr] = areg1.w;           \
    }

    unsigned long long acc[8][4];
#pragma unroll
    for (int r = 0; r < 8; r++)
#pragma unroll
        for (int c = 0; c < 4; c++) acc[r][c] = 0ULL;

    const int p0 = ((2 * cg) + ((2 * cg) >> 3)) * 4;
    const int p1 = ((2 * cg + 1) + ((2 * cg + 1) >> 3)) * 4;

    // prologue
    ISSUE_W(0, 0);
    LDG_A(0);
    STS_A(0);
    asm volatile("cp.async.wait_group 0;");
    __syncthreads();

#pragma unroll 1
    for (int ch = 0; ch < 16; ch++) {
        int cur = ch & 1;
        if (ch < 15) {
            ISSUE_W(ch + 1, cur ^ 1);
            LDG_A(ch + 1);
        }
        const float* saP = &sa[cur][0][rg * 8];
        const float* swP = &sw[cur][0][0];
#pragma unroll
        for (int kk = 0; kk < KC; kk++) {
            float4 aA = *(const float4*)(saP + kk * 68);
            float4 aB = *(const float4*)(saP + kk * 68 + 4);
            ulonglong2 w0 = *(const ulonglong2*)(swP + kk * 140 + p0);
            ulonglong2 w1 = *(const ulonglong2*)(swP + kk * 140 + p1);
            unsigned long long q;
            q = pk2(aA.x, aA.x); fma2(acc[0][0], q, w0.x); fma2(acc[0][1], q, w0.y); fma2(acc[0][2], q, w1.x); fma2(acc[0][3], q, w1.y);
            q = pk2(aA.y, aA.y); fma2(acc[1][0], q, w0.x); fma2(acc[1][1], q, w0.y); fma2(acc[1][2], q, w1.x); fma2(acc[1][3], q, w1.y);
            q = pk2(aA.z, aA.z); fma2(acc[2][0], q, w0.x); fma2(acc[2][1], q, w0.y); fma2(acc[2][2], q, w1.x); fma2(acc[2][3], q, w1.y);
            q = pk2(aA.w, aA.w); fma2(acc[3][0], q, w0.x); fma2(acc[3][1], q, w0.y); fma2(acc[3][2], q, w1.x); fma2(acc[3][3], q, w1.y);
            q = pk2(aB.x, aB.x); fma2(acc[4][0], q, w0.x); fma2(acc[4][1], q, w0.y); fma2(acc[4][2], q, w1.x); fma2(acc[4][3], q, w1.y);
            q = pk2(aB.y, aB.y); fma2(acc[5][0], q, w0.x); fma2(acc[5][1], q, w0.y); fma2(acc[5][2], q, w1.x); fma2(acc[5][3], q, w1.y);
            q = pk2(aB.z, aB.z); fma2(acc[6][0], q, w0.x); fma2(acc[6][1], q, w0.y); fma2(acc[6][2], q, w1.x); fma2(acc[6][3], q, w1.y);
            q = pk2(aB.w, aB.w); fma2(acc[7][0], q, w0.x); fma2(acc[7][1], q, w0.y); fma2(acc[7][2], q, w1.x); fma2(acc[7][3], q, w1.y);
        }
        if (ch < 15) {
            STS_A(cur ^ 1);
            asm volatile("cp.async.wait_group 0;");
            __syncthreads();
        }
    }

    // epilogue
    float bcol[8];
#pragma unroll
    for (int j = 0; j < 8; j++) bcol[j] = bias[colBase + cg * 8 + j];
#pragma unroll
    for (int r = 0; r < 8; r++) {
        int m = rowBase + rg * 8 + r;
        int b = m >> logR, pi = m & Rm1;
        float* dst;
        if (MODE == 2) dst = g_duo + (b * NN + 2 * (off + pi) + 1 + y) * 256;
        else           dst = g_duo + (b * NN + (off + pi)) * 256 + 128;
        float o[8];
#pragma unroll
        for (int c2 = 0; c2 < 4; c2++) {
            float v0, v1;
            unpk2(acc[r][c2], v0, v1);
            o[2 * c2]     = tanh_fast(v0 + bcol[2 * c2]);
            o[2 * c2 + 1] = tanh_fast(v1 + bcol[2 * c2 + 1]);
        }
        *(float4*)&dst[cg * 8]     = make_float4(o[0], o[1], o[2], o[3]);
        *(float4*)&dst[cg * 8 + 4] = make_float4(o[4], o[5], o[6], o[7]);
    }
#undef ISSUE_W
#undef LDG_A
#undef STS_A
}

// ---------- fused top of tree: up 3..0, gate, down 0..2 (smem weights) ----------
__global__ __launch_bounds__(256) void kmid(const float* __restrict__ bc,
                                            const float* __restrict__ bd,
                                            const float* __restrict__ bg) {
    extern __shared__ float dynW[];        // 128KB staging: WcT, then WgT, then WdT[0:128][:]
    __shared__ float su[31 * 128];
    __shared__ float sd[15 * 128];
    int b = blockIdx.x;
    int tid = threadIdx.x;
    float* duoB = g_duo + (long long)b * NN * 256;

    // load WcT (256x128 = 32768 floats) + init su leaves of the fused region
    for (int i = tid; i < 32768 / 4; i += 256)
        ((float4*)dynW)[i] = ((const float4*)g_WcT)[i];
    for (int idx = tid; idx < 16 * 128; idx += 256) {
        int n = 15 + (idx >> 7), c = idx & 127;
        su[n * 128 + c] = duoB[n * 256 + 128 + c];
    }
    __syncthreads();

    // upward levels 3..0 (weights from smem)
    for (int k = 3; k >= 0; --k) {
        int p0 = (1 << k) - 1, P = 1 << k;
        int col = tid & 127;
        for (int pi = tid >> 7; pi < P; pi += 2) {
            int p = p0 + pi;
            const float* ctx = &su[(2 * p + 1) * 128];
            float a0 = bc[col], a1 = 0.f, a2 = 0.f, a3 = 0.f;
#pragma unroll 8
            for (int j = 0; j < 256; j += 4) {
                a0 = fmaf(ctx[j + 0], dynW[(j + 0) * 128 + col], a0);
                a1 = fmaf(ctx[j + 1], dynW[(j + 1) * 128 + col], a1);
                a2 = fmaf(ctx[j + 2], dynW[(j + 2) * 128 + col], a2);
                a3 = fmaf(ctx[j + 3], dynW[(j + 3) * 128 + col], a3);
            }
            float v = tanh_fast((a0 + a1) + (a2 + a3));
            su[p * 128 + col] = v;
            duoB[p * 256 + 128 + col] = v;
        }
        __syncthreads();
    }

    // swap in WgT (128x128 = 16384 floats)
    for (int i = tid; i < 16384 / 4; i += 256)
        ((float4*)dynW)[i] = ((const float4*)g_WgT)[i];
    __syncthreads();

    // root gate
    if (tid < 128) {
        int col = tid;
        float a0 = bg[col], a1 = 0.f, a2 = 0.f, a3 = 0.f;
#pragma unroll 8
        for (int j = 0; j < 128; j += 4) {
            a0 = fmaf(su[j + 0], dynW[(j + 0) * 128 + col], a0);
            a1 = fmaf(su[j + 1], dynW[(j + 1) * 128 + col], a1);
            a2 = fmaf(su[j + 2], dynW[(j + 2) * 128 + col], a2);
            a3 = fmaf(su[j + 3], dynW[(j + 3) * 128 + col], a3);
        }
        float v = sigmoid_fast((a0 + a1) + (a2 + a3));
        sd[col] = v;
        duoB[col] = v;
    }
    __syncthreads();

    // swap in WdT rows 0..127 (down-ctx half: 128x256 = 32768 floats)
    for (int i = tid; i < 32768 / 4; i += 256)
        ((float4*)dynW)[i] = ((const float4*)g_WdT)[i];
    __syncthreads();

    // downward levels 0..2 (down-ctx from smem, up-ctx from L2)
    for (int k = 0; k <= 2; ++k) {
        int p0 = (1 << k) - 1, P = 1 << k;
        int col = tid;
        for (int pi = 0; pi < P; ++pi) {
            int p = p0 + pi;
            const float* dctx = &sd[p * 128];
            const float* uctx = &su[p * 128];
            float a0 = bd[col], a1 = 0.f, a2 = 0.f, a3 = 0.f;
#pragma unroll 8
            for (int j = 0; j < 128; j += 4) {
                a0 = fmaf(dctx[j + 0], dynW[(j + 0) * 256 + col], a0);
                a1 = fmaf(dctx[j + 1], dynW[(j + 1) * 256 + col], a1);
                a2 = fmaf(dctx[j + 2], dynW[(j + 2) * 256 + col], a2);
                a3 = fmaf(dctx[j + 3], dynW[(j + 3) * 256 + col], a3);
            }
#pragma unroll 8
            for (int j = 0; j < 128; j += 4) {
                a0 = fmaf(uctx[j + 0], g_WdT[(128 + j + 0) * 256 + col], a0);
                a1 = fmaf(uctx[j + 1], g_WdT[(128 + j + 1) * 256 + col], a1);
                a2 = fmaf(uctx[j + 2], g_WdT[(128 + j + 2) * 256 + col], a2);
                a3 = fmaf(uctx[j + 3], g_WdT[(128 + j + 3) * 256 + col], a3);
            }
            float v = tanh_fast((a0 + a1) + (a2 + a3));
            int child = 2 * p + 1 + (col >> 7);
            int cc = col & 127;
            sd[child * 128 + cc] = v;
            duoB[child * 256 + cc] = v;
        }
        __syncthreads();
    }
}

// ---------- classifier + softmax (one warp per node) ----------
__global__ __launch_bounds__(256) void kcls(const float* __restrict__ Wcl,
                                            const float* __restrict__ bcl,
                                            float* __restrict__ out) {
    int warp = (blockIdx.x * 256 + threadIdx.x) >> 5;
    int lane = threadIdx.x & 31;
    if (warp >= BB * NN) return;
    const float* row = g_duo + (long long)warp * 256;
    float s0 = 0.f, s1 = 0.f;
#pragma unroll
    for (int h = 0; h < 2; ++h) {
        float4 v = *(const float4*)&row[lane * 8 + h * 4];
        float4 a = *(const float4*)&Wcl[lane * 8 + h * 4];
        float4 c = *(const float4*)&Wcl[256 + lane * 8 + h * 4];
        s0 += v.x * a.x + v.y * a.y + v.z * a.z + v.w * a.w;
        s1 += v.x * c.x + v.y * c.y + v.z * c.z + v.w * c.w;
    }
#pragma unroll
    for (int o = 16; o; o >>= 1) {
        s0 += __shfl_xor_sync(0xFFFFFFFFu, s0, o);
        s1 += __shfl_xor_sync(0xFFFFFFFFu, s1, o);
    }
    if (lane == 0) {
        s0 = sigmoid_fast(s0 + bcl[0]);
        s1 = sigmoid_fast(s1 + bcl[1]);
        float e0 = __expf(s0), e1 = __expf(s1);
        float inv = __fdividef(1.0f, e0 + e1);
        out[warp * 2 + 0] = e0 * inv;
        out[warp * 2 + 1] = e1 * inv;
    }
}

extern "C" void kernel_launch(void* const* d_in, const int* in_sizes, int n_in,
                              void* d_out, int out_size) {
    const int*   x    = (const int*)d_in[0];
    const int*   cue  = (const int*)d_in[2];
    const float* emb  = (const float*)d_in[4];
    const float* Wc   = (const float*)d_in[5];
    const float* bc   = (const float*)d_in[6];
    const float* Wd   = (const float*)d_in[7];
    const float* bd   = (const float*)d_in[8];
    const float* Wg   = (const float*)d_in[9];
    const float* bg   = (const float*)d_in[10];
    const float* Wcl  = (const float*)d_in[11];
    const float* bcl  = (const float*)d_in[12];
    float* out = (float*)d_out;

    static int s_attr_done = 0;
    if (!s_attr_done) {
        cudaFuncSetAttribute(kmid, cudaFuncAttributeMaxDynamicSharedMemorySize, 131072);
        s_attr_done = 1;
    }

    ksetup<<<(BB * LL * 128) / 256, 256>>>(x, cue, emb, Wc, Wd, Wg);

    // upward
    kgemm2<0><<<dim3(128, 1), 128>>>(0, bc, 8, 255, 128);
    kgemm2<1><<<dim3(64, 1), 128>>>(0, bc, 7, 127, 128);
    kgemm2<1><<<dim3(32, 1), 128>>>(0, bc, 6, 63, 128);
    kgemm2<1><<<dim3(16, 1), 128>>>(0, bc, 5, 31, 128);
    kgemm2<1><<<dim3(8, 1), 128>>>(0, bc, 4, 15, 128);

    kmid<<<BB, 256, 131072>>>(bc, bd, bg);

    // downward
    kgemm2<2><<<dim3(4, 2), 128>>>(1, bd, 3, 7, 256);
    kgemm2<2><<<dim3(8, 2), 128>>>(1, bd, 4, 15, 256);
    kgemm2<2><<<dim3(16, 2), 128>>>(1, bd, 5, 31, 256);
    kgemm2<2><<<dim3(32, 2), 128>>>(1, bd, 6, 63, 256);
    kgemm2<2><<<dim3(64, 2), 128>>>(1, bd, 7, 127, 256);
    kgemm2<2><<<dim3(128, 2), 128>>>(1, bd, 8, 255, 256);

    kcls<<<(BB * NN + 7) / 8, 256>>>(Wcl, bcl, out);
}

// round 5
// speedup vs baseline: 2.1408x; 1.6417x over previous
#include <cuda_runtime.h>
#include <math.h>

#define BB 32
#define LL 512
#define NN 1023
#define EE 126
#define KC 16

// Scratch (device globals — no allocations allowed)
__device__ float g_duo[BB * NN * 256];   // [b][node][0:128 down | 128:256 up]
__device__ float g_leaf[BB * LL * 128];  // leaf input features
__device__ float g_WcT[256 * 128];       // WcT[j][i] = Wc[i][j]
__device__ float g_WdT[256 * 256];
__device__ float g_WgT[128 * 128];

// ---------- f32x2 helpers ----------
__device__ __forceinline__ unsigned long long pk2(float lo, float hi) {
    unsigned long long r;
    asm("mov.b64 %0, {%1,%2};" : "=l"(r) : "f"(lo), "f"(hi));
    return r;
}
__device__ __forceinline__ void fma2(unsigned long long& d, unsigned long long a, unsigned long long b) {
    asm("fma.rn.f32x2 %0, %1, %2, %0;" : "+l"(d) : "l"(a), "l"(b));
}
__device__ __forceinline__ void unpk2(unsigned long long v, float& a, float& b) {
    asm("mov.b64 {%0,%1}, %2;" : "=f"(a), "=f"(b) : "l"(v));
}
__device__ __forceinline__ float tanh_fast(float x) {
    float e = __expf(2.0f * x);
    return 1.0f - __fdividef(2.0f, e + 1.0f);
}
__device__ __forceinline__ float sigmoid_fast(float x) {
    return __fdividef(1.0f, 1.0f + __expf(-x));
}

// ---------- setup: weight transposes + leaf features + leaf up=0 ----------
__global__ __launch_bounds__(256) void ksetup(const int* __restrict__ x,
                                              const int* __restrict__ cue,
                                              const float* __restrict__ emb,
                                              const float* __restrict__ Wc,
                                              const float* __restrict__ Wd,
                                              const float* __restrict__ Wg) {
    int t = blockIdx.x * 256 + threadIdx.x;
    if (t < BB * LL * 128) {
        int i = t & 127;
        int l = (t >> 7) & (LL - 1);
        int b = t >> 16;
        int node = (LL - 1) + l;
        float v;
        if (i < EE) v = emb[(long long)x[b * NN + node] * EE + i];
        else        v = (cue[b * NN + node] == (i - EE)) ? 1.0f : 0.0f;
        g_leaf[t] = v;
        g_duo[(b * NN + node) * 256 + 128 + i] = 0.0f;
    }
    int stride = gridDim.x * 256;
    for (int idx = t; idx < 256 * 128; idx += stride) {
        int j = idx >> 7, i = idx & 127;
        g_WcT[idx] = Wc[i * 256 + j];
    }
    for (int idx = t; idx < 256 * 256; idx += stride) {
        int j = idx >> 8, i = idx & 255;
        g_WdT[idx] = Wd[i * 256 + j];
    }
    for (int idx = t; idx < 128 * 128; idx += stride) {
        int j = idx >> 7, i = idx & 127;
        g_WgT[idx] = Wg[i * 128 + j];
    }
}

// ---------- occupancy-first level GEMM ----------
// OUT[M, 128-tile] = tanh(A[M,256] @ WT[:, colBase:colBase+128] + bias)
// Block: 256 threads (2 warps/SMSP); tile RT rows x 128 cols; thread: TR=RT/16 rows x 8 cols.
// MODE 0: up d=8, A from g_leaf (contiguous 256)
// MODE 1: up d<8, A = concat(up[2p+1], up[2p+2])
// MODE 2: down,   A = duo row of parent (contiguous 256); y picks child/col-half
template <int MODE, int RT>
__global__ __launch_bounds__(256, 2) void kgemm3(int sel, const float* __restrict__ bias,
                                                 int logR, int off, int Ntot) {
    constexpr int TR = RT / 16;         // rows per thread
    constexpr int NL = RT * 4;          // A-loader thread count (RT*KC/4 float4s)
    __shared__ __align__(16) float sa[2][KC][RT + 4];
    __shared__ __align__(16) float sw[2][KC][140];
    const float* __restrict__ WT = sel ? g_WdT : g_WcT;
    const int tid = threadIdx.x;
    const int cg = tid & 15;       // col group: cols cg*8 .. cg*8+7
    const int rg = tid >> 4;       // row group: rows rg*TR .. rg*TR+TR-1
    const int y = blockIdx.y;
    const int colBase = y << 7;
    const int rowBase = blockIdx.x * RT;
    const int Rm1 = (1 << logR) - 1;

    // A loader: thread (tid < NL) handles row lr, k-quarterchunk q*4
    const int lr = tid >> 2;
    const int qk = (tid & 3) * 4;
    const float* abase = nullptr;
    if (tid < NL) {
        int m = rowBase + lr;
        int b = m >> logR, pi = m & Rm1;
        if (MODE == 0)      abase = g_leaf + (((b << 9) + (pi << 1)) << 7);
        else if (MODE == 1) abase = g_duo + (b * NN + 2 * (off + pi) + 1) * 256 + 128;
        else                abase = g_duo + (b * NN + (off + pi)) * 256;
    }
    unsigned swbase = (unsigned)__cvta_generic_to_shared(&sw[0][0][0]);

    float4 areg;

#define ISSUE_W(CH, BUF)                                                              \
    {                                                                                 \
        _Pragma("unroll")                                                             \
        for (int i = 0; i < 2; i++) {                                                 \
            int f = tid + i * 256;                                                    \
            int kk = f >> 5, c4 = f & 31;                                             \
            const float* src = WT + ((CH) * KC + kk) * Ntot + colBase + c4 * 4;       \
            unsigned dst = swbase + ((BUF) * KC * 140 + kk * 140 + (c4 + (c4 >> 3)) * 4) * 4; \
            asm volatile("cp.async.cg.shared.global [%0], [%1], 16;" ::"r"(dst), "l"(src)); \
        }                                                                             \
        asm volatile("cp.async.commit_group;");                                       \
    }

#define LDG_A(CH)                                                                     \
    if (tid < NL) {                                                                   \
        int k = (CH) * KC + qk;                                                       \
        int extra = (MODE == 1) ? ((k >> 7) << 7) : 0;                                \
        areg = *(const float4*)(abase + k + extra);                                   \
    }

#define STS_A(BUF)                                                                    \
    if (tid < NL) {                                                                   \
        sa[BUF][qk + 0][lr] = areg.x; sa[BUF][qk + 1][lr] = areg.y;                   \
        sa[BUF][qk + 2][lr] = areg.z; sa[BUF][qk + 3][lr] = areg.w;                   \
    }

    unsigned long long acc[TR][4];
#pragma unroll
    for (int r = 0; r < TR; r++)
#pragma unroll
        for (int c = 0; c < 4; c++) acc[r][c] = 0ULL;

    const int p0 = ((2 * cg) + ((2 * cg) >> 3)) * 4;
    const int p1 = ((2 * cg + 1) + ((2 * cg + 1) >> 3)) * 4;

    // prologue
    ISSUE_W(0, 0);
    LDG_A(0);
    STS_A(0);
    asm volatile("cp.async.wait_group 0;");
    __syncthreads();

#pragma unroll 1
    for (int ch = 0; ch < 16; ch++) {
        int cur = ch & 1;
        if (ch < 15) {
            ISSUE_W(ch + 1, cur ^ 1);
            LDG_A(ch + 1);
        }
        const float* saP = &sa[cur][0][rg * TR];
        const float* swP = &sw[cur][0][0];
#pragma unroll
        for (int kk = 0; kk < KC; kk++) {
            ulonglong2 w0 = *(const ulonglong2*)(swP + kk * 140 + p0);
            ulonglong2 w1 = *(const ulonglong2*)(swP + kk * 140 + p1);
            if (TR == 4) {
                float4 aA = *(const float4*)(saP + kk * (RT + 4));
                unsigned long long q;
                q = pk2(aA.x, aA.x); fma2(acc[0][0], q, w0.x); fma2(acc[0][1], q, w0.y); fma2(acc[0][2], q, w1.x); fma2(acc[0][3], q, w1.y);
                q = pk2(aA.y, aA.y); fma2(acc[1][0], q, w0.x); fma2(acc[1][1], q, w0.y); fma2(acc[1][2], q, w1.x); fma2(acc[1][3], q, w1.y);
                q = pk2(aA.z, aA.z); fma2(acc[2][0], q, w0.x); fma2(acc[2][1], q, w0.y); fma2(acc[2][2], q, w1.x); fma2(acc[2][3], q, w1.y);
                q = pk2(aA.w, aA.w); fma2(acc[3][0], q, w0.x); fma2(acc[3][1], q, w0.y); fma2(acc[3][2], q, w1.x); fma2(acc[3][3], q, w1.y);
            } else {
                float2 aA = *(const float2*)(saP + kk * (RT + 4));
                unsigned long long q;
                q = pk2(aA.x, aA.x); fma2(acc[0][0], q, w0.x); fma2(acc[0][1], q, w0.y); fma2(acc[0][2], q, w1.x); fma2(acc[0][3], q, w1.y);
                q = pk2(aA.y, aA.y); fma2(acc[1][0], q, w0.x); fma2(acc[1][1], q, w0.y); fma2(acc[1][2], q, w1.x); fma2(acc[1][3], q, w1.y);
            }
        }
        if (ch < 15) {
            STS_A(cur ^ 1);
            asm volatile("cp.async.wait_group 0;");
            __syncthreads();
        }
    }

    // epilogue
    float bcol[8];
#pragma unroll
    for (int j = 0; j < 8; j++) bcol[j] = bias[colBase + cg * 8 + j];
#pragma unroll
    for (int r = 0; r < TR; r++) {
        int m = rowBase + rg * TR + r;
        int b = m >> logR, pi = m & Rm1;
        float* dst;
        if (MODE == 2) dst = g_duo + (b * NN + 2 * (off + pi) + 1 + y) * 256;
        else           dst = g_duo + (b * NN + (off + pi)) * 256 + 128;
        float o[8];
#pragma unroll
        for (int c2 = 0; c2 < 4; c2++) {
            float v0, v1;
            unpk2(acc[r][c2], v0, v1);
            o[2 * c2]     = tanh_fast(v0 + bcol[2 * c2]);
            o[2 * c2 + 1] = tanh_fast(v1 + bcol[2 * c2 + 1]);
        }
        *(float4*)&dst[cg * 8]     = make_float4(o[0], o[1], o[2], o[3]);
        *(float4*)&dst[cg * 8 + 4] = make_float4(o[4], o[5], o[6], o[7]);
    }
#undef ISSUE_W
#undef LDG_A
#undef STS_A
}

// ---------- fused top of tree: up 3..0, gate, down 0..2 (smem weights) ----------
__global__ __launch_bounds__(256) void kmid(const float* __restrict__ bc,
                                            const float* __restrict__ bd,
                                            const float* __restrict__ bg) {
    extern __shared__ float dynW[];        // 128KB staging: WcT, then WgT, then WdT[0:128][:]
    __shared__ float su[31 * 128];
    __shared__ float sd[15 * 128];
    int b = blockIdx.x;
    int tid = threadIdx.x;
    float* duoB = g_duo + (long long)b * NN * 256;

    for (int i = tid; i < 32768 / 4; i += 256)
        ((float4*)dynW)[i] = ((const float4*)g_WcT)[i];
    for (int idx = tid; idx < 16 * 128; idx += 256) {
        int n = 15 + (idx >> 7), c = idx & 127;
        su[n * 128 + c] = duoB[n * 256 + 128 + c];
    }
    __syncthreads();

    // upward levels 3..0 (weights from smem)
    for (int k = 3; k >= 0; --k) {
        int p0 = (1 << k) - 1, P = 1 << k;
        int col = tid & 127;
        for (int pi = tid >> 7; pi < P; pi += 2) {
            int p = p0 + pi;
            const float* ctx = &su[(2 * p + 1) * 128];
            float a0 = bc[col], a1 = 0.f, a2 = 0.f, a3 = 0.f;
#pragma unroll 8
            for (int j = 0; j < 256; j += 4) {
                a0 = fmaf(ctx[j + 0], dynW[(j + 0) * 128 + col], a0);
                a1 = fmaf(ctx[j + 1], dynW[(j + 1) * 128 + col], a1);
                a2 = fmaf(ctx[j + 2], dynW[(j + 2) * 128 + col], a2);
                a3 = fmaf(ctx[j + 3], dynW[(j + 3) * 128 + col], a3);
            }
            float v = tanh_fast((a0 + a1) + (a2 + a3));
            su[p * 128 + col] = v;
            duoB[p * 256 + 128 + col] = v;
        }
        __syncthreads();
    }

    // swap in WgT
    for (int i = tid; i < 16384 / 4; i += 256)
        ((float4*)dynW)[i] = ((const float4*)g_WgT)[i];
    __syncthreads();

    // root gate
    if (tid < 128) {
        int col = tid;
        float a0 = bg[col], a1 = 0.f, a2 = 0.f, a3 = 0.f;
#pragma unroll 8
        for (int j = 0; j < 128; j += 4) {
            a0 = fmaf(su[j + 0], dynW[(j + 0) * 128 + col], a0);
            a1 = fmaf(su[j + 1], dynW[(j + 1) * 128 + col], a1);
            a2 = fmaf(su[j + 2], dynW[(j + 2) * 128 + col], a2);
            a3 = fmaf(su[j + 3], dynW[(j + 3) * 128 + col], a3);
        }
        float v = sigmoid_fast((a0 + a1) + (a2 + a3));
        sd[col] = v;
        duoB[col] = v;
    }
    __syncthreads();

    // swap in WdT rows 0..127 (down-ctx half)
    for (int i = tid; i < 32768 / 4; i += 256)
        ((float4*)dynW)[i] = ((const float4*)g_WdT)[i];
    __syncthreads();

    // downward levels 0..2 (down-ctx from smem, up-ctx from L2)
    for (int k = 0; k <= 2; ++k) {
        int p0 = (1 << k) - 1, P = 1 << k;
        int col = tid;
        for (int pi = 0; pi < P; ++pi) {
            int p = p0 + pi;
            const float* dctx = &sd[p * 128];
            const float* uctx = &su[p * 128];
            float a0 = bd[col], a1 = 0.f, a2 = 0.f, a3 = 0.f;
#pragma unroll 8
            for (int j = 0; j < 128; j += 4) {
                a0 = fmaf(dctx[j + 0], dynW[(j + 0) * 256 + col], a0);
                a1 = fmaf(dctx[j + 1], dynW[(j + 1) * 256 + col], a1);
                a2 = fmaf(dctx[j + 2], dynW[(j + 2) * 256 + col], a2);
                a3 = fmaf(dctx[j + 3], dynW[(j + 3) * 256 + col], a3);
            }
#pragma unroll 8
            for (int j = 0; j < 128; j += 4) {
                a0 = fmaf(uctx[j + 0], g_WdT[(128 + j + 0) * 256 + col], a0);
                a1 = fmaf(uctx[j + 1], g_WdT[(128 + j + 1) * 256 + col], a1);
                a2 = fmaf(uctx[j + 2], g_WdT[(128 + j + 2) * 256 + col], a2);
                a3 = fmaf(uctx[j + 3], g_WdT[(128 + j + 3) * 256 + col], a3);
            }
            float v = tanh_fast((a0 + a1) + (a2 + a3));
            int child = 2 * p + 1 + (col >> 7);
            int cc = col & 127;
            sd[child * 128 + cc] = v;
            duoB[child * 256 + cc] = v;
        }
        __syncthreads();
    }
}

// ---------- classifier + softmax (one warp per node) ----------
__global__ __launch_bounds__(256) void kcls(const float* __restrict__ Wcl,
                                            const float* __restrict__ bcl,
                                            float* __restrict__ out) {
    int warp = (blockIdx.x * 256 + threadIdx.x) >> 5;
    int lane = threadIdx.x & 31;
    if (warp >= BB * NN) return;
    const float* row = g_duo + (long long)warp * 256;
    float s0 = 0.f, s1 = 0.f;
#pragma unroll
    for (int h = 0; h < 2; ++h) {
        float4 v = *(const float4*)&row[lane * 8 + h * 4];
        float4 a = *(const float4*)&Wcl[lane * 8 + h * 4];
        float4 c = *(const float4*)&Wcl[256 + lane * 8 + h * 4];
        s0 += v.x * a.x + v.y * a.y + v.z * a.z + v.w * a.w;
        s1 += v.x * c.x + v.y * c.y + v.z * c.z + v.w * c.w;
    }
#pragma unroll
    for (int o = 16; o; o >>= 1) {
        s0 += __shfl_xor_sync(0xFFFFFFFFu, s0, o);
        s1 += __shfl_xor_sync(0xFFFFFFFFu, s1, o);
    }
    if (lane == 0) {
        s0 = sigmoid_fast(s0 + bcl[0]);
        s1 = sigmoid_fast(s1 + bcl[1]);
        float e0 = __expf(s0), e1 = __expf(s1);
        float inv = __fdividef(1.0f, e0 + e1);
        out[warp * 2 + 0] = e0 * inv;
        out[warp * 2 + 1] = e1 * inv;
    }
}

extern "C" void kernel_launch(void* const* d_in, const int* in_sizes, int n_in,
                              void* d_out, int out_size) {
    const int*   x    = (const int*)d_in[0];
    const int*   cue  = (const int*)d_in[2];
    const float* emb  = (const float*)d_in[4];
    const float* Wc   = (const float*)d_in[5];
    const float* bc   = (const float*)d_in[6];
    const float* Wd   = (const float*)d_in[7];
    const float* bd   = (const float*)d_in[8];
    const float* Wg   = (const float*)d_in[9];
    const float* bg   = (const float*)d_in[10];
    const float* Wcl  = (const float*)d_in[11];
    const float* bcl  = (const float*)d_in[12];
    float* out = (float*)d_out;

    static int s_attr_done = 0;
    if (!s_attr_done) {
        cudaFuncSetAttribute(kmid, cudaFuncAttributeMaxDynamicSharedMemorySize, 131072);
        s_attr_done = 1;
    }

    ksetup<<<(BB * LL * 128) / 256, 256>>>(x, cue, emb, Wc, Wd, Wg);

    // upward
    kgemm3<0, 64><<<dim3(128, 1), 256>>>(0, bc, 8, 255, 128);  // M=8192
    kgemm3<1, 32><<<dim3(128, 1), 256>>>(0, bc, 7, 127, 128);  // M=4096
    kgemm3<1, 32><<<dim3(64, 1), 256>>>(0, bc, 6, 63, 128);    // M=2048
    kgemm3<1, 32><<<dim3(32, 1), 256>>>(0, bc, 5, 31, 128);    // M=1024
    kgemm3<1, 32><<<dim3(16, 1), 256>>>(0, bc, 4, 15, 128);    // M=512

    kmid<<<BB, 256, 131072>>>(bc, bd, bg);

    // downward
    kgemm3<2, 32><<<dim3(8, 2), 256>>>(1, bd, 3, 7, 256);      // M=256
    kgemm3<2, 32><<<dim3(16, 2), 256>>>(1, bd, 4, 15, 256);    // M=512
    kgemm3<2, 32><<<dim3(32, 2), 256>>>(1, bd, 5, 31, 256);    // M=1024
    kgemm3<2, 32><<<dim3(64, 2), 256>>>(1, bd, 6, 63, 256);    // M=2048
    kgemm3<2, 64><<<dim3(64, 2), 256>>>(1, bd, 7, 127, 256);   // M=4096
    kgemm3<2, 64><<<dim3(128, 2), 256>>>(1, bd, 8, 255, 256);  // M=8192

    kcls<<<(BB * NN + 7) / 8, 256>>>(Wcl, bcl, out);
}